// round 2
// baseline (speedup 1.0000x reference)
#include <cuda_runtime.h>
#include <math.h>

#define SQ   2048   // sequence length
#define CCH  2048   // channels
#define NH   16     // heads
#define HD   128    // head dim
#define BLKS 64     // block size
#define NB   32     // num blocks
#define THRP 0.8f
#define EPSV 1e-6f

// ---------------- scratch (device globals; no allocation allowed) -------------
__device__ float g_q[SQ * CCH];
__device__ float g_k[SQ * CCH];
__device__ float g_v[SQ * CCH];
__device__ float g_attn[SQ * CCH];
__device__ float g_qb[NH * NB * HD];
__device__ float g_kb[NH * NB * HD];
__device__ unsigned char g_mask[NH * NB * NB];

// ---------------- GEMM: C = A(MxK) @ B(KxN) + bias(N) -------------------------
__global__ __launch_bounds__(256) void gemm_bias(
    const float* __restrict__ A, const float* __restrict__ B,
    const float* __restrict__ bias, float* __restrict__ Co,
    int M, int N, int K)
{
    __shared__ float As[16][64];
    __shared__ float Bs[16][64];
    int tid = threadIdx.x;
    int m0 = blockIdx.y * 64, n0 = blockIdx.x * 64;
    int ty = tid >> 4, tx = tid & 15;

    int ar = tid >> 2, aq = tid & 3;     // A tile: row ar (0..63), float4 col aq (0..3)
    int br = tid >> 4, bq4 = tid & 15;   // B tile: row br (0..15), float4 col bq4 (0..15)

    float acc[4][4];
#pragma unroll
    for (int i = 0; i < 4; i++)
#pragma unroll
        for (int j = 0; j < 4; j++) acc[i][j] = 0.f;

    for (int k0 = 0; k0 < K; k0 += 16) {
        float4 a4 = *(const float4*)(A + (size_t)(m0 + ar) * K + k0 + aq * 4);
        As[aq * 4 + 0][ar] = a4.x;
        As[aq * 4 + 1][ar] = a4.y;
        As[aq * 4 + 2][ar] = a4.z;
        As[aq * 4 + 3][ar] = a4.w;
        float4 b4 = *(const float4*)(B + (size_t)(k0 + br) * N + n0 + bq4 * 4);
        *(float4*)&Bs[br][bq4 * 4] = b4;
        __syncthreads();
#pragma unroll
        for (int kk = 0; kk < 16; kk++) {
            float4 av = *(float4*)&As[kk][ty * 4];
            float4 bv = *(float4*)&Bs[kk][tx * 4];
            float am[4] = {av.x, av.y, av.z, av.w};
            float bn[4] = {bv.x, bv.y, bv.z, bv.w};
#pragma unroll
            for (int i = 0; i < 4; i++)
#pragma unroll
                for (int j = 0; j < 4; j++) acc[i][j] += am[i] * bn[j];
        }
        __syncthreads();
    }
#pragma unroll
    for (int i = 0; i < 4; i++) {
        float* crow = Co + (size_t)(m0 + ty * 4 + i) * N + n0 + tx * 4;
#pragma unroll
        for (int j = 0; j < 4; j++)
            crow[j] = acc[i][j] + bias[n0 + tx * 4 + j];
    }
}

// ---------------- fused RMSNorm + RoPE, in-place on [S, H*D] -------------------
// one warp per (s, h) row of 128 elems; lane owns d in {lane, lane+32, lane+64, lane+96}
__global__ __launch_bounds__(256) void rmsnorm_rope(
    float* __restrict__ buf, const float* __restrict__ w,
    const float* __restrict__ cs, const float* __restrict__ sn)
{
    int warp = (blockIdx.x * blockDim.x + threadIdx.x) >> 5;
    int lane = threadIdx.x & 31;
    if (warp >= SQ * NH) return;
    int s = warp / NH, h = warp % NH;
    float* row = buf + (size_t)s * CCH + h * HD;

    float x0 = row[lane], x1 = row[lane + 32], x2 = row[lane + 64], x3 = row[lane + 96];
    float ss = x0 * x0 + x1 * x1 + x2 * x2 + x3 * x3;
#pragma unroll
    for (int o = 16; o; o >>= 1) ss += __shfl_xor_sync(0xffffffffu, ss, o);
    float r = rsqrtf(ss * (1.0f / HD) + EPSV);

    float y0 = x0 * r * w[lane];
    float y1 = x1 * r * w[lane + 32];
    float y2 = x2 * r * w[lane + 64];
    float y3 = x3 * r * w[lane + 96];

    const float* cr = cs + (size_t)s * HD;
    const float* sr = sn + (size_t)s * HD;
    // rotate_half: d<64 -> -y[d+64]; d>=64 -> y[d-64]
    row[lane]      = y0 * cr[lane]      - y2 * sr[lane];
    row[lane + 32] = y1 * cr[lane + 32] - y3 * sr[lane + 32];
    row[lane + 64] = y2 * cr[lane + 64] + y0 * sr[lane + 64];
    row[lane + 96] = y3 * cr[lane + 96] + y1 * sr[lane + 96];
}

// ---------------- block pooling: out[h][b][d] = mean over 64 rows --------------
__global__ void pool_blocks(const float* __restrict__ buf, float* __restrict__ out)
{
    int h = blockIdx.x, b = blockIdx.y, d = threadIdx.x;  // 128 threads
    float sum = 0.f;
#pragma unroll 8
    for (int i = 0; i < BLKS; i++)
        sum += buf[(size_t)(b * BLKS + i) * CCH + h * HD + d];
    out[((h * NB) + b) * HD + d] = sum * (1.0f / BLKS);
}

// ---------------- NABLA block mask ---------------------------------------------
// sta_mask arrives as an unknown dtype (bool converted by the harness to int32,
// float32, or kept as 1-byte). Sniff it device-side, deterministically.
__device__ __forceinline__ int sniff_sta_dtype(const unsigned int* w)
{
    // Examine the first 256 32-bit words (covers the whole buffer if int32/f32,
    // or the whole buffer if uint8). Classify:
    //   all words in {0,1}            -> int32 bools
    //   all words in {0, 0x3F800000}  -> float32 bools
    //   otherwise                     -> packed uint8 bools
    bool all01 = true, allf = true;
    for (int i = 0; i < 256; i++) {
        unsigned int v = w[i];
        if (v > 1u) all01 = false;
        if (v != 0u && v != 0x3F800000u) allf = false;
    }
    if (all01) return 0;
    if (allf) return 1;
    return 2;
}

__global__ void nabla_mask(const float* __restrict__ qb, const float* __restrict__ kb,
                           const void* __restrict__ sta, unsigned char* __restrict__ mask)
{
    int h = blockIdx.x, q = blockIdx.y, k = threadIdx.x;  // 32 threads
    __shared__ float p[NB];
    __shared__ float cutoff;
    __shared__ int sdt;
    if (k == 0) sdt = sniff_sta_dtype((const unsigned int*)sta);

    const float* qr = qb + (h * NB + q) * HD;
    const float* kr = kb + (h * NB + k) * HD;
    float dot = 0.f;
#pragma unroll 16
    for (int d = 0; d < HD; d++) dot += qr[d] * kr[d];
    p[k] = dot * 0.08838834764831845f;  // 1/sqrt(128)
    __syncthreads();
    if (k == 0) {
        float mx = -1e30f;
        for (int i = 0; i < NB; i++) mx = fmaxf(mx, p[i]);
        float sum = 0.f;
        for (int i = 0; i < NB; i++) { p[i] = expf(p[i] - mx); sum += p[i]; }
        float inv = 1.0f / sum;
        float srt[NB];
        for (int i = 0; i < NB; i++) { p[i] *= inv; srt[i] = p[i]; }
        // insertion sort descending
        for (int i = 1; i < NB; i++) {
            float v = srt[i];
            int j = i - 1;
            while (j >= 0 && srt[j] < v) { srt[j + 1] = srt[j]; j--; }
            srt[j + 1] = v;
        }
        float run = 0.f, co = 1e30f;
        for (int i = 0; i < NB; i++) {
            if (run < THRP) { co = srt[i]; run += srt[i]; }
        }
        cutoff = co;
    }
    __syncthreads();

    bool sta_on;
    int sidx = q * NB + k;
    if (sdt == 0)      sta_on = ((const int*)sta)[sidx] != 0;
    else if (sdt == 1) sta_on = ((const float*)sta)[sidx] != 0.0f;
    else               sta_on = ((const unsigned char*)sta)[sidx] != 0;

    unsigned char keep = (p[k] >= cutoff) || sta_on;
    mask[(h * NB + q) * NB + k] = keep;
}

// ---------------- block-sparse flash attention ----------------------------------
// grid (NB, NH); 256 threads; thread t handles q-row = t/4, d-lane dseg = t&3,
// owning d = dseg + 4*j (j<32) and score cols kk = dseg + 4*j (j<16).
#define QKV_STR 132
#define P_STR   65
#define FA_SMEM ((3 * 64 * QKV_STR + 64 * P_STR) * 4)

__global__ __launch_bounds__(256) void flash_attn(
    const float* __restrict__ q, const float* __restrict__ k, const float* __restrict__ v,
    const unsigned char* __restrict__ mask, float* __restrict__ o)
{
    extern __shared__ float sm[];
    float* Qs = sm;
    float* Ks = Qs + 64 * QKV_STR;
    float* Vs = Ks + 64 * QKV_STR;
    float* Ps = Vs + 64 * QKV_STR;

    int qi = blockIdx.x, h = blockIdx.y;
    int tid = threadIdx.x;
    int qr = tid >> 2, dseg = tid & 3;

    for (int idx = tid; idx < 64 * 32; idx += 256) {
        int r = idx >> 5, c = idx & 31;
        *(float4*)&Qs[r * QKV_STR + c * 4] =
            *(const float4*)(q + (size_t)(qi * 64 + r) * CCH + h * HD + c * 4);
    }

    float acc[32];
#pragma unroll
    for (int j = 0; j < 32; j++) acc[j] = 0.f;
    float mrow = -INFINITY, lrow = 0.f;
    const unsigned char* mrowp = mask + (h * NB + qi) * NB;
    const float scl = 0.08838834764831845f;

    for (int kb = 0; kb < NB; kb++) {
        if (!mrowp[kb]) continue;
        __syncthreads();  // protect smem reuse (and Q readiness on first pass)
        for (int idx = tid; idx < 64 * 32; idx += 256) {
            int r = idx >> 5, c = idx & 31;
            *(float4*)&Ks[r * QKV_STR + c * 4] =
                *(const float4*)(k + (size_t)(kb * 64 + r) * CCH + h * HD + c * 4);
            *(float4*)&Vs[r * QKV_STR + c * 4] =
                *(const float4*)(v + (size_t)(kb * 64 + r) * CCH + h * HD + c * 4);
        }
        __syncthreads();

        float sc[16];
#pragma unroll
        for (int j = 0; j < 16; j++) sc[j] = 0.f;
        for (int d = 0; d < HD; d++) {
            float qv = Qs[qr * QKV_STR + d];
#pragma unroll
            for (int j = 0; j < 16; j++)
                sc[j] += qv * Ks[(dseg + 4 * j) * QKV_STR + d];
        }
        float rmax = -INFINITY;
#pragma unroll
        for (int j = 0; j < 16; j++) { sc[j] *= scl; rmax = fmaxf(rmax, sc[j]); }
#pragma unroll
        for (int off = 1; off < 4; off <<= 1)
            rmax = fmaxf(rmax, __shfl_xor_sync(0xffffffffu, rmax, off));
        float mnew = fmaxf(mrow, rmax);
        float scale = expf(mrow - mnew);
        float rsum = 0.f;
#pragma unroll
        for (int j = 0; j < 16; j++) {
            float pv = expf(sc[j] - mnew);
            Ps[qr * P_STR + dseg + 4 * j] = pv;
            rsum += pv;
        }
#pragma unroll
        for (int off = 1; off < 4; off <<= 1)
            rsum += __shfl_xor_sync(0xffffffffu, rsum, off);
        lrow = lrow * scale + rsum;
        mrow = mnew;
#pragma unroll
        for (int j = 0; j < 32; j++) acc[j] *= scale;
        __syncthreads();  // Ps visible

        for (int kk = 0; kk < 64; kk++) {
            float pv = Ps[qr * P_STR + kk];
            const float* vr = &Vs[kk * QKV_STR + dseg];
#pragma unroll
            for (int j = 0; j < 32; j++) acc[j] += pv * vr[4 * j];
        }
    }

    float invl = 1.0f / lrow;
    float* orow = o + (size_t)(qi * 64 + qr) * CCH + h * HD + dseg;
#pragma unroll
    for (int j = 0; j < 32; j++) orow[4 * j] = acc[j] * invl;
}

// ---------------- launch ---------------------------------------------------------
extern "C" void kernel_launch(void* const* d_in, const int* in_sizes, int n_in,
                              void* d_out, int out_size)
{
    const float* x        = (const float*)d_in[0];
    const float* rope_cos = (const float*)d_in[1];
    const float* rope_sin = (const float*)d_in[2];
    const void*  sta      = (const void*)d_in[3];
    const float* Wq = (const float*)d_in[4];
    const float* bq = (const float*)d_in[5];
    const float* Wk = (const float*)d_in[6];
    const float* bk = (const float*)d_in[7];
    const float* Wv = (const float*)d_in[8];
    const float* bv = (const float*)d_in[9];
    const float* Wo = (const float*)d_in[10];
    const float* bo = (const float*)d_in[11];
    const float* qn_w = (const float*)d_in[12];
    const float* kn_w = (const float*)d_in[13];
    float* out = (float*)d_out;

    float *qp, *kp, *vp, *ap, *qbp, *kbp;
    unsigned char* mp;
    cudaGetSymbolAddress((void**)&qp, g_q);
    cudaGetSymbolAddress((void**)&kp, g_k);
    cudaGetSymbolAddress((void**)&vp, g_v);
    cudaGetSymbolAddress((void**)&ap, g_attn);
    cudaGetSymbolAddress((void**)&qbp, g_qb);
    cudaGetSymbolAddress((void**)&kbp, g_kb);
    cudaGetSymbolAddress((void**)&mp, g_mask);

    dim3 ggrid(CCH / 64, SQ / 64);
    gemm_bias<<<ggrid, 256>>>(x, Wq, bq, qp, SQ, CCH, CCH);
    gemm_bias<<<ggrid, 256>>>(x, Wk, bk, kp, SQ, CCH, CCH);
    gemm_bias<<<ggrid, 256>>>(x, Wv, bv, vp, SQ, CCH, CCH);

    int nwarp_blocks = (SQ * NH) / 8;  // 8 warps per block
    rmsnorm_rope<<<nwarp_blocks, 256>>>(qp, qn_w, rope_cos, rope_sin);
    rmsnorm_rope<<<nwarp_blocks, 256>>>(kp, kn_w, rope_cos, rope_sin);

    pool_blocks<<<dim3(NH, NB), 128>>>(qp, qbp);
    pool_blocks<<<dim3(NH, NB), 128>>>(kp, kbp);

    nabla_mask<<<dim3(NH, NB), 32>>>(qbp, kbp, sta, mp);

    cudaFuncSetAttribute(flash_attn, cudaFuncAttributeMaxDynamicSharedMemorySize, FA_SMEM);
    flash_attn<<<dim3(NB, NH), 256, FA_SMEM>>>(qp, kp, vp, mp, ap);

    gemm_bias<<<ggrid, 256>>>(ap, Wo, bo, out, SQ, CCH, CCH);
}

// round 5
// speedup vs baseline: 1.2217x; 1.2217x over previous
#include <cuda_runtime.h>
#include <cuda_bf16.h>
#include <math.h>

#define SQ   2048
#define CCH  2048
#define NH   16
#define HD   128
#define BLKS 64
#define NB   32
#define THRP 0.8f
#define EPSV 1e-6f

// ---------------- scratch (device globals; no allocation allowed) -------------
__device__ float g_q[SQ * CCH];
__device__ float g_k[SQ * CCH];
__device__ float g_v[SQ * CCH];
__device__ float g_attn[SQ * CCH];
__device__ float g_qb[NH * NB * HD];
__device__ float g_kb[NH * NB * HD];
__device__ unsigned char g_mask[NH * NB * NB];

// bf16 split buffers (stored as ushort)
__device__ unsigned short g_xh[SQ * CCH];
__device__ unsigned short g_xl[SQ * CCH];
__device__ unsigned short g_ah[SQ * CCH];
__device__ unsigned short g_al[SQ * CCH];
__device__ unsigned short g_wqh[CCH * CCH];
__device__ unsigned short g_wql[CCH * CCH];
__device__ unsigned short g_wkh[CCH * CCH];
__device__ unsigned short g_wkl[CCH * CCH];
__device__ unsigned short g_wvh[CCH * CCH];
__device__ unsigned short g_wvl[CCH * CCH];
__device__ unsigned short g_woh[CCH * CCH];
__device__ unsigned short g_wol[CCH * CCH];

// ================= fp32 -> bf16 hi/lo split ====================================
__global__ void split_bf16(const float* __restrict__ a, unsigned short* __restrict__ h,
                           unsigned short* __restrict__ l, int n)
{
    int i = blockIdx.x * 256 + threadIdx.x;
    if (i < n) {
        float v = a[i];
        __nv_bfloat16 hi = __float2bfloat16(v);
        __nv_bfloat16 lo = __float2bfloat16(v - __bfloat162float(hi));
        h[i] = __bfloat16_as_ushort(hi);
        l[i] = __bfloat16_as_ushort(lo);
    }
}

// ================= transpose + split: W[K][N] -> T[N][K] hi/lo bf16 ============
__global__ void transpose_split(const float* __restrict__ W,
                                unsigned short* __restrict__ Th, unsigned short* __restrict__ Tl)
{
    __shared__ float t[32][33];
    int bx = blockIdx.x * 32, by = blockIdx.y * 32;
    int tx = threadIdx.x, ty = threadIdx.y;
    t[ty][tx] = W[(size_t)(by + ty) * CCH + bx + tx];
    __syncthreads();
    float v = t[tx][ty];  // = W[by+tx][bx+ty]
    __nv_bfloat16 hi = __float2bfloat16(v);
    __nv_bfloat16 lo = __float2bfloat16(v - __bfloat162float(hi));
    size_t o = (size_t)(bx + ty) * CCH + by + tx;
    Th[o] = __bfloat16_as_ushort(hi);
    Tl[o] = __bfloat16_as_ushort(lo);
}

// ================= HMMA bf16x3 GEMM: C[M,N] = A[M,K] @ B^T + bias ==============
// A row-major [M][K], B row-major [N][K] (pre-transposed). mma m16n8k16 row.col.
#define BM 128
#define BN 64
#define BK 32
#define ASTR 40   // padded bf16 row stride in smem (conflict-free frag loads)

__device__ __forceinline__ void mma_bf16(float* c, const unsigned* a, const unsigned* b)
{
    asm volatile(
        "mma.sync.aligned.m16n8k16.row.col.f32.bf16.bf16.f32 "
        "{%0,%1,%2,%3}, {%4,%5,%6,%7}, {%8,%9}, {%0,%1,%2,%3};"
        : "+f"(c[0]), "+f"(c[1]), "+f"(c[2]), "+f"(c[3])
        : "r"(a[0]), "r"(a[1]), "r"(a[2]), "r"(a[3]), "r"(b[0]), "r"(b[1]));
}

__global__ __launch_bounds__(256) void gemm_tc(
    const unsigned short* __restrict__ Ah, const unsigned short* __restrict__ Al,
    const unsigned short* __restrict__ Bh, const unsigned short* __restrict__ Bl,
    const float* __restrict__ bias, float* __restrict__ Co)
{
    __shared__ __align__(16) unsigned short Ahs[BM * ASTR];
    __shared__ __align__(16) unsigned short Als[BM * ASTR];
    __shared__ __align__(16) unsigned short Bhs[BN * ASTR];
    __shared__ __align__(16) unsigned short Bls[BN * ASTR];

    int tid = threadIdx.x, w = tid >> 5, lane = tid & 31;
    int g = lane >> 2, tc2 = (lane & 3) * 2;
    int m0 = blockIdx.y * BM, n0 = blockIdx.x * BN;
    int wm = (w >> 1) * 32, wn = (w & 1) * 32;

    float acc[2][4][4];
#pragma unroll
    for (int i = 0; i < 2; i++)
#pragma unroll
        for (int j = 0; j < 4; j++)
#pragma unroll
            for (int l = 0; l < 4; l++) acc[i][j][l] = 0.f;

    int ra = tid >> 1, hf = (tid & 1) * 8;    // A loads: row, two 8-col chunks (hf, hf+16)
    int rb = tid >> 2, qb = (tid & 3) * 8;    // B loads: row, 8-col quarter

    for (int ck = 0; ck < CCH / BK; ck++) {
        int kb = ck * BK;
        const unsigned short* arow_h = Ah + (size_t)(m0 + ra) * CCH + kb;
        const unsigned short* arow_l = Al + (size_t)(m0 + ra) * CCH + kb;
        *(uint4*)&Ahs[ra * ASTR + hf]      = *(const uint4*)(arow_h + hf);
        *(uint4*)&Ahs[ra * ASTR + hf + 16] = *(const uint4*)(arow_h + hf + 16);
        *(uint4*)&Als[ra * ASTR + hf]      = *(const uint4*)(arow_l + hf);
        *(uint4*)&Als[ra * ASTR + hf + 16] = *(const uint4*)(arow_l + hf + 16);
        *(uint4*)&Bhs[rb * ASTR + qb] = *(const uint4*)(Bh + (size_t)(n0 + rb) * CCH + kb + qb);
        *(uint4*)&Bls[rb * ASTR + qb] = *(const uint4*)(Bl + (size_t)(n0 + rb) * CCH + kb + qb);
        __syncthreads();

#pragma unroll
        for (int ks = 0; ks < BK; ks += 16) {
            unsigned ah[2][4], al[2][4], bh[4][2], bl[4][2];
#pragma unroll
            for (int mf = 0; mf < 2; mf++) {
                int r = (wm + mf * 16 + g) * ASTR;
                ah[mf][0] = *(const unsigned*)&Ahs[r + ks + tc2];
                ah[mf][1] = *(const unsigned*)&Ahs[r + 8 * ASTR + ks + tc2];
                ah[mf][2] = *(const unsigned*)&Ahs[r + ks + 8 + tc2];
                ah[mf][3] = *(const unsigned*)&Ahs[r + 8 * ASTR + ks + 8 + tc2];
                al[mf][0] = *(const unsigned*)&Als[r + ks + tc2];
                al[mf][1] = *(const unsigned*)&Als[r + 8 * ASTR + ks + tc2];
                al[mf][2] = *(const unsigned*)&Als[r + ks + 8 + tc2];
                al[mf][3] = *(const unsigned*)&Als[r + 8 * ASTR + ks + 8 + tc2];
            }
#pragma unroll
            for (int nf = 0; nf < 4; nf++) {
                int r = (wn + nf * 8 + g) * ASTR;
                bh[nf][0] = *(const unsigned*)&Bhs[r + ks + tc2];
                bh[nf][1] = *(const unsigned*)&Bhs[r + ks + 8 + tc2];
                bl[nf][0] = *(const unsigned*)&Bls[r + ks + tc2];
                bl[nf][1] = *(const unsigned*)&Bls[r + ks + 8 + tc2];
            }
#pragma unroll
            for (int mf = 0; mf < 2; mf++)
#pragma unroll
                for (int nf = 0; nf < 4; nf++) {
                    mma_bf16(acc[mf][nf], ah[mf], bh[nf]);
                    mma_bf16(acc[mf][nf], ah[mf], bl[nf]);
                    mma_bf16(acc[mf][nf], al[mf], bh[nf]);
                }
        }
        __syncthreads();
    }

#pragma unroll
    for (int mf = 0; mf < 2; mf++) {
        int r0 = m0 + wm + mf * 16 + g;
#pragma unroll
        for (int nf = 0; nf < 4; nf++) {
            int col = n0 + wn + nf * 8 + tc2;
            float bx = bias[col], by = bias[col + 1];
            float2 lo = make_float2(acc[mf][nf][0] + bx, acc[mf][nf][1] + by);
            float2 hi = make_float2(acc[mf][nf][2] + bx, acc[mf][nf][3] + by);
            *(float2*)(Co + (size_t)r0 * CCH + col) = lo;
            *(float2*)(Co + (size_t)(r0 + 8) * CCH + col) = hi;
        }
    }
}

// ---------------- fused RMSNorm + RoPE, in-place on [S, H*D] -------------------
__global__ __launch_bounds__(256) void rmsnorm_rope(
    float* __restrict__ buf, const float* __restrict__ w,
    const float* __restrict__ cs, const float* __restrict__ sn)
{
    int warp = (blockIdx.x * blockDim.x + threadIdx.x) >> 5;
    int lane = threadIdx.x & 31;
    if (warp >= SQ * NH) return;
    int s = warp / NH, h = warp % NH;
    float* row = buf + (size_t)s * CCH + h * HD;

    float x0 = row[lane], x1 = row[lane + 32], x2 = row[lane + 64], x3 = row[lane + 96];
    float ss = x0 * x0 + x1 * x1 + x2 * x2 + x3 * x3;
#pragma unroll
    for (int o = 16; o; o >>= 1) ss += __shfl_xor_sync(0xffffffffu, ss, o);
    float r = rsqrtf(ss * (1.0f / HD) + EPSV);

    float y0 = x0 * r * w[lane];
    float y1 = x1 * r * w[lane + 32];
    float y2 = x2 * r * w[lane + 64];
    float y3 = x3 * r * w[lane + 96];

    const float* cr = cs + (size_t)s * HD;
    const float* sr = sn + (size_t)s * HD;
    row[lane]      = y0 * cr[lane]      - y2 * sr[lane];
    row[lane + 32] = y1 * cr[lane + 32] - y3 * sr[lane + 32];
    row[lane + 64] = y2 * cr[lane + 64] + y0 * sr[lane + 64];
    row[lane + 96] = y3 * cr[lane + 96] + y1 * sr[lane + 96];
}

// ---------------- block pooling ------------------------------------------------
__global__ void pool_blocks(const float* __restrict__ buf, float* __restrict__ out)
{
    int h = blockIdx.x, b = blockIdx.y, d = threadIdx.x;
    float sum = 0.f;
#pragma unroll 8
    for (int i = 0; i < BLKS; i++)
        sum += buf[(size_t)(b * BLKS + i) * CCH + h * HD + d];
    out[((h * NB) + b) * HD + d] = sum * (1.0f / BLKS);
}

// ---------------- NABLA block mask ----------------------------------------------
__device__ __forceinline__ int sniff_sta_dtype(const unsigned int* w)
{
    bool all01 = true, allf = true;
    for (int i = 0; i < 256; i++) {
        unsigned int v = w[i];
        if (v > 1u) all01 = false;
        if (v != 0u && v != 0x3F800000u) allf = false;
    }
    if (all01) return 0;
    if (allf) return 1;
    return 2;
}

__global__ void nabla_mask(const float* __restrict__ qb, const float* __restrict__ kb,
                           const void* __restrict__ sta, unsigned char* __restrict__ mask)
{
    int h = blockIdx.x, q = blockIdx.y, k = threadIdx.x;
    __shared__ float p[NB];
    __shared__ float cutoff;
    __shared__ int sdt;
    if (k == 0) sdt = sniff_sta_dtype((const unsigned int*)sta);

    const float* qr = qb + (h * NB + q) * HD;
    const float* kr = kb + (h * NB + k) * HD;
    float dot = 0.f;
#pragma unroll 16
    for (int d = 0; d < HD; d++) dot += qr[d] * kr[d];
    p[k] = dot * 0.08838834764831845f;
    __syncthreads();
    if (k == 0) {
        float mx = -1e30f;
        for (int i = 0; i < NB; i++) mx = fmaxf(mx, p[i]);
        float sum = 0.f;
        for (int i = 0; i < NB; i++) { p[i] = expf(p[i] - mx); sum += p[i]; }
        float inv = 1.0f / sum;
        float srt[NB];
        for (int i = 0; i < NB; i++) { p[i] *= inv; srt[i] = p[i]; }
        for (int i = 1; i < NB; i++) {
            float v = srt[i];
            int j = i - 1;
            while (j >= 0 && srt[j] < v) { srt[j + 1] = srt[j]; j--; }
            srt[j + 1] = v;
        }
        float run = 0.f, co = 1e30f;
        for (int i = 0; i < NB; i++) {
            if (run < THRP) { co = srt[i]; run += srt[i]; }
        }
        cutoff = co;
    }
    __syncthreads();

    bool sta_on;
    int sidx = q * NB + k;
    if (sdt == 0)      sta_on = ((const int*)sta)[sidx] != 0;
    else if (sdt == 1) sta_on = ((const float*)sta)[sidx] != 0.0f;
    else               sta_on = ((const unsigned char*)sta)[sidx] != 0;

    unsigned char keep = (p[k] >= cutoff) || sta_on;
    mask[(h * NB + q) * NB + k] = keep;
}

// ---------------- block-sparse flash attention -----------------------------------
#define QKV_STR 132
#define P_STR   65
#define FA_SMEM ((3 * 64 * QKV_STR + 64 * P_STR) * 4)

__global__ __launch_bounds__(256) void flash_attn(
    const float* __restrict__ q, const float* __restrict__ k, const float* __restrict__ v,
    const unsigned char* __restrict__ mask, float* __restrict__ o)
{
    extern __shared__ float smf[];
    float* Qs = smf;
    float* Ks = Qs + 64 * QKV_STR;
    float* Vs = Ks + 64 * QKV_STR;
    float* Ps = Vs + 64 * QKV_STR;

    int qi = blockIdx.x, h = blockIdx.y;
    int tid = threadIdx.x;
    int qr = tid >> 2, dseg = tid & 3;

    for (int idx = tid; idx < 64 * 32; idx += 256) {
        int r = idx >> 5, c = idx & 31;
        *(float4*)&Qs[r * QKV_STR + c * 4] =
            *(const float4*)(q + (size_t)(qi * 64 + r) * CCH + h * HD + c * 4);
    }

    float acc[32];
#pragma unroll
    for (int j = 0; j < 32; j++) acc[j] = 0.f;
    float mrow = -INFINITY, lrow = 0.f;
    const unsigned char* mrowp = mask + (h * NB + qi) * NB;
    const float scl = 0.08838834764831845f;

    for (int kb = 0; kb < NB; kb++) {
        if (!mrowp[kb]) continue;
        __syncthreads();
        for (int idx = tid; idx < 64 * 32; idx += 256) {
            int r = idx >> 5, c = idx & 31;
            *(float4*)&Ks[r * QKV_STR + c * 4] =
                *(const float4*)(k + (size_t)(kb * 64 + r) * CCH + h * HD + c * 4);
            *(float4*)&Vs[r * QKV_STR + c * 4] =
                *(const float4*)(v + (size_t)(kb * 64 + r) * CCH + h * HD + c * 4);
        }
        __syncthreads();

        float sc[16];
#pragma unroll
        for (int j = 0; j < 16; j++) sc[j] = 0.f;
        for (int d = 0; d < HD; d++) {
            float qv = Qs[qr * QKV_STR + d];
#pragma unroll
            for (int j = 0; j < 16; j++)
                sc[j] += qv * Ks[(dseg + 4 * j) * QKV_STR + d];
        }
        float rmax = -INFINITY;
#pragma unroll
        for (int j = 0; j < 16; j++) { sc[j] *= scl; rmax = fmaxf(rmax, sc[j]); }
#pragma unroll
        for (int off = 1; off < 4; off <<= 1)
            rmax = fmaxf(rmax, __shfl_xor_sync(0xffffffffu, rmax, off));
        float mnew = fmaxf(mrow, rmax);
        float scale = expf(mrow - mnew);
        float rsum = 0.f;
#pragma unroll
        for (int j = 0; j < 16; j++) {
            float pv = expf(sc[j] - mnew);
            Ps[qr * P_STR + dseg + 4 * j] = pv;
            rsum += pv;
        }
#pragma unroll
        for (int off = 1; off < 4; off <<= 1)
            rsum += __shfl_xor_sync(0xffffffffu, rsum, off);
        lrow = lrow * scale + rsum;
        mrow = mnew;
#pragma unroll
        for (int j = 0; j < 32; j++) acc[j] *= scale;
        __syncthreads();

        for (int kk = 0; kk < 64; kk++) {
            float pv = Ps[qr * P_STR + kk];
            const float* vr = &Vs[kk * QKV_STR + dseg];
#pragma unroll
            for (int j = 0; j < 32; j++) acc[j] += pv * vr[4 * j];
        }
    }

    float invl = 1.0f / lrow;
    float* orow = o + (size_t)(qi * 64 + qr) * CCH + h * HD + dseg;
#pragma unroll
    for (int j = 0; j < 32; j++) orow[4 * j] = acc[j] * invl;
}

// ---------------- launch ----------------------------------------------------------
extern "C" void kernel_launch(void* const* d_in, const int* in_sizes, int n_in,
                              void* d_out, int out_size)
{
    const float* x        = (const float*)d_in[0];
    const float* rope_cos = (const float*)d_in[1];
    const float* rope_sin = (const float*)d_in[2];
    const void*  sta      = (const void*)d_in[3];
    const float* Wq = (const float*)d_in[4];
    const float* bq = (const float*)d_in[5];
    const float* Wk = (const float*)d_in[6];
    const float* bk = (const float*)d_in[7];
    const float* Wv = (const float*)d_in[8];
    const float* bv = (const float*)d_in[9];
    const float* Wo = (const float*)d_in[10];
    const float* bo = (const float*)d_in[11];
    const float* qn_w = (const float*)d_in[12];
    const float* kn_w = (const float*)d_in[13];
    float* out = (float*)d_out;

    float *qp, *kp, *vp, *ap, *qbp, *kbp;
    unsigned char* mp;
    unsigned short *xh, *xl, *ah, *al;
    unsigned short *wqh, *wql, *wkh, *wkl, *wvh, *wvl, *woh, *wol;
    cudaGetSymbolAddress((void**)&qp, g_q);
    cudaGetSymbolAddress((void**)&kp, g_k);
    cudaGetSymbolAddress((void**)&vp, g_v);
    cudaGetSymbolAddress((void**)&ap, g_attn);
    cudaGetSymbolAddress((void**)&qbp, g_qb);
    cudaGetSymbolAddress((void**)&kbp, g_kb);
    cudaGetSymbolAddress((void**)&mp, g_mask);
    cudaGetSymbolAddress((void**)&xh, g_xh);
    cudaGetSymbolAddress((void**)&xl, g_xl);
    cudaGetSymbolAddress((void**)&ah, g_ah);
    cudaGetSymbolAddress((void**)&al, g_al);
    cudaGetSymbolAddress((void**)&wqh, g_wqh);
    cudaGetSymbolAddress((void**)&wql, g_wql);
    cudaGetSymbolAddress((void**)&wkh, g_wkh);
    cudaGetSymbolAddress((void**)&wkl, g_wkl);
    cudaGetSymbolAddress((void**)&wvh, g_wvh);
    cudaGetSymbolAddress((void**)&wvl, g_wvl);
    cudaGetSymbolAddress((void**)&woh, g_woh);
    cudaGetSymbolAddress((void**)&wol, g_wol);

    const int NEL = SQ * CCH;
    dim3 tgrid(CCH / 32, CCH / 32), tblk(32, 32);

    split_bf16<<<(NEL + 255) / 256, 256>>>(x, xh, xl, NEL);
    transpose_split<<<tgrid, tblk>>>(Wq, wqh, wql);
    transpose_split<<<tgrid, tblk>>>(Wk, wkh, wkl);
    transpose_split<<<tgrid, tblk>>>(Wv, wvh, wvl);
    transpose_split<<<tgrid, tblk>>>(Wo, woh, wol);

    dim3 ggrid(CCH / BN, SQ / BM);
    gemm_tc<<<ggrid, 256>>>(xh, xl, wqh, wql, bq, qp);
    gemm_tc<<<ggrid, 256>>>(xh, xl, wkh, wkl, bk, kp);
    gemm_tc<<<ggrid, 256>>>(xh, xl, wvh, wvl, bv, vp);

    int nwarp_blocks = (SQ * NH) / 8;
    rmsnorm_rope<<<nwarp_blocks, 256>>>(qp, qn_w, rope_cos, rope_sin);
    rmsnorm_rope<<<nwarp_blocks, 256>>>(kp, kn_w, rope_cos, rope_sin);

    pool_blocks<<<dim3(NH, NB), 128>>>(qp, qbp);
    pool_blocks<<<dim3(NH, NB), 128>>>(kp, kbp);

    nabla_mask<<<dim3(NH, NB), 32>>>(qbp, kbp, sta, mp);

    cudaFuncSetAttribute(flash_attn, cudaFuncAttributeMaxDynamicSharedMemorySize, FA_SMEM);
    flash_attn<<<dim3(NB, NH), 256, FA_SMEM>>>(qp, kp, vp, mp, ap);

    split_bf16<<<(NEL + 255) / 256, 256>>>(ap, ah, al, NEL);
    gemm_tc<<<ggrid, 256>>>(ah, al, woh, wol, bo, out);
}

// round 6
// speedup vs baseline: 2.6589x; 2.1764x over previous
#include <cuda_runtime.h>
#include <cuda_bf16.h>
#include <math.h>

#define SQ   2048
#define CCH  2048
#define NH   16
#define HD   128
#define BLKS 64
#define NB   32
#define THRP 0.8f
#define EPSV 1e-6f

// ---------------- scratch (device globals; no allocation allowed) -------------
__device__ float g_q[SQ * CCH];
__device__ float g_k[SQ * CCH];
__device__ float g_v[SQ * CCH];
__device__ float g_attn[SQ * CCH];
__device__ float g_qb[NH * NB * HD];
__device__ float g_kb[NH * NB * HD];
__device__ unsigned char g_mask[NH * NB * NB];

// bf16 split buffers (stored as ushort)
__device__ unsigned short g_xh[SQ * CCH];
__device__ unsigned short g_xl[SQ * CCH];
__device__ unsigned short g_ah[SQ * CCH];
__device__ unsigned short g_al[SQ * CCH];
__device__ unsigned short g_qsh[SQ * CCH];
__device__ unsigned short g_qsl[SQ * CCH];
__device__ unsigned short g_ksh[SQ * CCH];
__device__ unsigned short g_ksl[SQ * CCH];
__device__ unsigned short g_vsh[SQ * CCH];
__device__ unsigned short g_vsl[SQ * CCH];
__device__ unsigned short g_wqh[CCH * CCH];
__device__ unsigned short g_wql[CCH * CCH];
__device__ unsigned short g_wkh[CCH * CCH];
__device__ unsigned short g_wkl[CCH * CCH];
__device__ unsigned short g_wvh[CCH * CCH];
__device__ unsigned short g_wvl[CCH * CCH];
__device__ unsigned short g_woh[CCH * CCH];
__device__ unsigned short g_wol[CCH * CCH];

// ================= helpers ======================================================
__device__ __forceinline__ unsigned pack_bf16x2(float lo, float hi) {
    unsigned r;
    asm("cvt.rn.bf16x2.f32 %0, %1, %2;" : "=r"(r) : "f"(hi), "f"(lo));
    return r;
}
__device__ __forceinline__ unsigned smem_u32(const void* p) {
    unsigned a;
    asm("{ .reg .u64 t; cvta.to.shared.u64 t, %1; cvt.u32.u64 %0, t; }" : "=r"(a) : "l"(p));
    return a;
}
__device__ __forceinline__ void mma_bf16(float* c, const unsigned* a, const unsigned* b)
{
    asm volatile(
        "mma.sync.aligned.m16n8k16.row.col.f32.bf16.bf16.f32 "
        "{%0,%1,%2,%3}, {%4,%5,%6,%7}, {%8,%9}, {%0,%1,%2,%3};"
        : "+f"(c[0]), "+f"(c[1]), "+f"(c[2]), "+f"(c[3])
        : "r"(a[0]), "r"(a[1]), "r"(a[2]), "r"(a[3]), "r"(b[0]), "r"(b[1]));
}
__device__ __forceinline__ void ldsm_x4_t(unsigned& r0, unsigned& r1, unsigned& r2, unsigned& r3,
                                          unsigned addr)
{
    asm volatile("ldmatrix.sync.aligned.m8n8.x4.trans.shared.b16 {%0,%1,%2,%3}, [%4];"
                 : "=r"(r0), "=r"(r1), "=r"(r2), "=r"(r3) : "r"(addr));
}

// ================= fp32 -> bf16 hi/lo split ====================================
__global__ void split_bf16(const float* __restrict__ a, unsigned short* __restrict__ h,
                           unsigned short* __restrict__ l, int n)
{
    int i = blockIdx.x * 256 + threadIdx.x;
    if (i < n) {
        float v = a[i];
        __nv_bfloat16 hi = __float2bfloat16(v);
        __nv_bfloat16 lo = __float2bfloat16(v - __bfloat162float(hi));
        h[i] = __bfloat16_as_ushort(hi);
        l[i] = __bfloat16_as_ushort(lo);
    }
}

// ================= transpose + split: W[K][N] -> T[N][K] hi/lo bf16 ============
__global__ void transpose_split(const float* __restrict__ W,
                                unsigned short* __restrict__ Th, unsigned short* __restrict__ Tl)
{
    __shared__ float t[32][33];
    int bx = blockIdx.x * 32, by = blockIdx.y * 32;
    int tx = threadIdx.x, ty = threadIdx.y;
    t[ty][tx] = W[(size_t)(by + ty) * CCH + bx + tx];
    __syncthreads();
    float v = t[tx][ty];
    __nv_bfloat16 hi = __float2bfloat16(v);
    __nv_bfloat16 lo = __float2bfloat16(v - __bfloat162float(hi));
    size_t o = (size_t)(bx + ty) * CCH + by + tx;
    Th[o] = __bfloat16_as_ushort(hi);
    Tl[o] = __bfloat16_as_ushort(lo);
}

// ================= HMMA bf16x3 GEMM: C[M,N] = A[M,K] @ B^T + bias ==============
#define BM 128
#define BN 64
#define BK 32
#define ASTR 40

__global__ __launch_bounds__(256) void gemm_tc(
    const unsigned short* __restrict__ Ah, const unsigned short* __restrict__ Al,
    const unsigned short* __restrict__ Bh, const unsigned short* __restrict__ Bl,
    const float* __restrict__ bias, float* __restrict__ Co)
{
    __shared__ __align__(16) unsigned short Ahs[BM * ASTR];
    __shared__ __align__(16) unsigned short Als[BM * ASTR];
    __shared__ __align__(16) unsigned short Bhs[BN * ASTR];
    __shared__ __align__(16) unsigned short Bls[BN * ASTR];

    int tid = threadIdx.x, w = tid >> 5, lane = tid & 31;
    int g = lane >> 2, tc2 = (lane & 3) * 2;
    int m0 = blockIdx.y * BM, n0 = blockIdx.x * BN;
    int wm = (w >> 1) * 32, wn = (w & 1) * 32;

    float acc[2][4][4];
#pragma unroll
    for (int i = 0; i < 2; i++)
#pragma unroll
        for (int j = 0; j < 4; j++)
#pragma unroll
            for (int l = 0; l < 4; l++) acc[i][j][l] = 0.f;

    int ra = tid >> 1, hf = (tid & 1) * 8;
    int rb = tid >> 2, qb = (tid & 3) * 8;

    for (int ck = 0; ck < CCH / BK; ck++) {
        int kb = ck * BK;
        const unsigned short* arow_h = Ah + (size_t)(m0 + ra) * CCH + kb;
        const unsigned short* arow_l = Al + (size_t)(m0 + ra) * CCH + kb;
        *(uint4*)&Ahs[ra * ASTR + hf]      = *(const uint4*)(arow_h + hf);
        *(uint4*)&Ahs[ra * ASTR + hf + 16] = *(const uint4*)(arow_h + hf + 16);
        *(uint4*)&Als[ra * ASTR + hf]      = *(const uint4*)(arow_l + hf);
        *(uint4*)&Als[ra * ASTR + hf + 16] = *(const uint4*)(arow_l + hf + 16);
        *(uint4*)&Bhs[rb * ASTR + qb] = *(const uint4*)(Bh + (size_t)(n0 + rb) * CCH + kb + qb);
        *(uint4*)&Bls[rb * ASTR + qb] = *(const uint4*)(Bl + (size_t)(n0 + rb) * CCH + kb + qb);
        __syncthreads();

#pragma unroll
        for (int ks = 0; ks < BK; ks += 16) {
            unsigned ah[2][4], al[2][4], bh[4][2], bl[4][2];
#pragma unroll
            for (int mf = 0; mf < 2; mf++) {
                int r = (wm + mf * 16 + g) * ASTR;
                ah[mf][0] = *(const unsigned*)&Ahs[r + ks + tc2];
                ah[mf][1] = *(const unsigned*)&Ahs[r + 8 * ASTR + ks + tc2];
                ah[mf][2] = *(const unsigned*)&Ahs[r + ks + 8 + tc2];
                ah[mf][3] = *(const unsigned*)&Ahs[r + 8 * ASTR + ks + 8 + tc2];
                al[mf][0] = *(const unsigned*)&Als[r + ks + tc2];
                al[mf][1] = *(const unsigned*)&Als[r + 8 * ASTR + ks + tc2];
                al[mf][2] = *(const unsigned*)&Als[r + ks + 8 + tc2];
                al[mf][3] = *(const unsigned*)&Als[r + 8 * ASTR + ks + 8 + tc2];
            }
#pragma unroll
            for (int nf = 0; nf < 4; nf++) {
                int r = (wn + nf * 8 + g) * ASTR;
                bh[nf][0] = *(const unsigned*)&Bhs[r + ks + tc2];
                bh[nf][1] = *(const unsigned*)&Bhs[r + ks + 8 + tc2];
                bl[nf][0] = *(const unsigned*)&Bls[r + ks + tc2];
                bl[nf][1] = *(const unsigned*)&Bls[r + ks + 8 + tc2];
            }
#pragma unroll
            for (int mf = 0; mf < 2; mf++)
#pragma unroll
                for (int nf = 0; nf < 4; nf++) {
                    mma_bf16(acc[mf][nf], ah[mf], bh[nf]);
                    mma_bf16(acc[mf][nf], ah[mf], bl[nf]);
                    mma_bf16(acc[mf][nf], al[mf], bh[nf]);
                }
        }
        __syncthreads();
    }

#pragma unroll
    for (int mf = 0; mf < 2; mf++) {
        int r0 = m0 + wm + mf * 16 + g;
#pragma unroll
        for (int nf = 0; nf < 4; nf++) {
            int col = n0 + wn + nf * 8 + tc2;
            float bx = bias[col], by = bias[col + 1];
            float2 lo = make_float2(acc[mf][nf][0] + bx, acc[mf][nf][1] + by);
            float2 hi = make_float2(acc[mf][nf][2] + bx, acc[mf][nf][3] + by);
            *(float2*)(Co + (size_t)r0 * CCH + col) = lo;
            *(float2*)(Co + (size_t)(r0 + 8) * CCH + col) = hi;
        }
    }
}

// ---------------- fused RMSNorm + RoPE + bf16 split, in-place ------------------
__global__ __launch_bounds__(256) void rmsnorm_rope_split(
    float* __restrict__ buf, const float* __restrict__ w,
    const float* __restrict__ cs, const float* __restrict__ sn,
    unsigned short* __restrict__ oh, unsigned short* __restrict__ ol)
{
    int warp = (blockIdx.x * blockDim.x + threadIdx.x) >> 5;
    int lane = threadIdx.x & 31;
    if (warp >= SQ * NH) return;
    int s = warp / NH, h = warp % NH;
    size_t base = (size_t)s * CCH + h * HD;
    float* row = buf + base;

    float x0 = row[lane], x1 = row[lane + 32], x2 = row[lane + 64], x3 = row[lane + 96];
    float ss = x0 * x0 + x1 * x1 + x2 * x2 + x3 * x3;
#pragma unroll
    for (int o = 16; o; o >>= 1) ss += __shfl_xor_sync(0xffffffffu, ss, o);
    float r = rsqrtf(ss * (1.0f / HD) + EPSV);

    float y0 = x0 * r * w[lane];
    float y1 = x1 * r * w[lane + 32];
    float y2 = x2 * r * w[lane + 64];
    float y3 = x3 * r * w[lane + 96];

    const float* cr = cs + (size_t)s * HD;
    const float* sr = sn + (size_t)s * HD;
    float z0 = y0 * cr[lane]      - y2 * sr[lane];
    float z1 = y1 * cr[lane + 32] - y3 * sr[lane + 32];
    float z2 = y2 * cr[lane + 64] + y0 * sr[lane + 64];
    float z3 = y3 * cr[lane + 96] + y1 * sr[lane + 96];

    row[lane] = z0; row[lane + 32] = z1; row[lane + 64] = z2; row[lane + 96] = z3;

    float zz[4] = {z0, z1, z2, z3};
#pragma unroll
    for (int i = 0; i < 4; i++) {
        __nv_bfloat16 hi = __float2bfloat16(zz[i]);
        __nv_bfloat16 lo = __float2bfloat16(zz[i] - __bfloat162float(hi));
        oh[base + lane + 32 * i] = __bfloat16_as_ushort(hi);
        ol[base + lane + 32 * i] = __bfloat16_as_ushort(lo);
    }
}

// ---------------- block pooling ------------------------------------------------
__global__ void pool_blocks(const float* __restrict__ buf, float* __restrict__ out)
{
    int h = blockIdx.x, b = blockIdx.y, d = threadIdx.x;
    float sum = 0.f;
#pragma unroll 8
    for (int i = 0; i < BLKS; i++)
        sum += buf[(size_t)(b * BLKS + i) * CCH + h * HD + d];
    out[((h * NB) + b) * HD + d] = sum * (1.0f / BLKS);
}

// ---------------- NABLA block mask ----------------------------------------------
__device__ __forceinline__ int sniff_sta_dtype(const unsigned int* w)
{
    bool all01 = true, allf = true;
    for (int i = 0; i < 256; i++) {
        unsigned int v = w[i];
        if (v > 1u) all01 = false;
        if (v != 0u && v != 0x3F800000u) allf = false;
    }
    if (all01) return 0;
    if (allf) return 1;
    return 2;
}

__global__ void nabla_mask(const float* __restrict__ qb, const float* __restrict__ kb,
                           const void* __restrict__ sta, unsigned char* __restrict__ mask)
{
    int h = blockIdx.x, q = blockIdx.y, k = threadIdx.x;
    __shared__ float p[NB];
    __shared__ float cutoff;
    __shared__ int sdt;
    if (k == 0) sdt = sniff_sta_dtype((const unsigned int*)sta);

    const float* qr = qb + (h * NB + q) * HD;
    const float* kr = kb + (h * NB + k) * HD;
    float dot = 0.f;
#pragma unroll 16
    for (int d = 0; d < HD; d++) dot += qr[d] * kr[d];
    p[k] = dot * 0.08838834764831845f;
    __syncthreads();
    if (k == 0) {
        float mx = -1e30f;
        for (int i = 0; i < NB; i++) mx = fmaxf(mx, p[i]);
        float sum = 0.f;
        for (int i = 0; i < NB; i++) { p[i] = expf(p[i] - mx); sum += p[i]; }
        float inv = 1.0f / sum;
        float srt[NB];
        for (int i = 0; i < NB; i++) { p[i] *= inv; srt[i] = p[i]; }
        for (int i = 1; i < NB; i++) {
            float v = srt[i];
            int j = i - 1;
            while (j >= 0 && srt[j] < v) { srt[j + 1] = srt[j]; j--; }
            srt[j + 1] = v;
        }
        float run = 0.f, co = 1e30f;
        for (int i = 0; i < NB; i++) {
            if (run < THRP) { co = srt[i]; run += srt[i]; }
        }
        cutoff = co;
    }
    __syncthreads();

    bool sta_on;
    int sidx = q * NB + k;
    if (sdt == 0)      sta_on = ((const int*)sta)[sidx] != 0;
    else if (sdt == 1) sta_on = ((const float*)sta)[sidx] != 0.0f;
    else               sta_on = ((const unsigned char*)sta)[sidx] != 0;

    unsigned char keep = (p[k] >= cutoff) || sta_on;
    mask[(h * NB + q) * NB + k] = keep;
}

// ---------------- HMMA block-sparse flash attention ------------------------------
// 128 threads (4 warps), CTA = (q-block qi, head h). Warp w owns q rows w*16..+15.
#define KSTR 136   // ushort row stride for 64x128 tiles
#define FT_SMEM (4 * 64 * KSTR * 2)

__global__ __launch_bounds__(128) void flash_attn_tc(
    const unsigned short* __restrict__ qh, const unsigned short* __restrict__ ql,
    const unsigned short* __restrict__ kh, const unsigned short* __restrict__ kl,
    const unsigned short* __restrict__ vh, const unsigned short* __restrict__ vl,
    const unsigned char* __restrict__ mask, float* __restrict__ o)
{
    extern __shared__ __align__(16) unsigned short smu[];
    unsigned short* Kh = smu;
    unsigned short* Kl = Kh + 64 * KSTR;
    unsigned short* Vh = Kl + 64 * KSTR;
    unsigned short* Vl = Vh + 64 * KSTR;

    int qi = blockIdx.x, h = blockIdx.y;
    int tid = threadIdx.x, w = tid >> 5, lane = tid & 31;
    int g = lane >> 2, tc2 = (lane & 3) * 2;
    int wr = w * 16;

    // ---- load Q tile into Kh/Kl region, extract register fragments -------------
    for (int idx = tid; idx < 64 * 16; idx += 128) {
        int r = idx >> 4, c = (idx & 15) * 8;
        size_t off = (size_t)(qi * 64 + r) * CCH + h * HD + c;
        *(uint4*)&Kh[r * KSTR + c] = *(const uint4*)(qh + off);
        *(uint4*)&Kl[r * KSTR + c] = *(const uint4*)(ql + off);
    }
    __syncthreads();

    unsigned qfh[8][4], qfl[8][4];
#pragma unroll
    for (int t = 0; t < 8; t++) {
        int r0 = (wr + g) * KSTR + 16 * t + tc2;
        int r8 = (wr + 8 + g) * KSTR + 16 * t + tc2;
        qfh[t][0] = *(const unsigned*)&Kh[r0];
        qfh[t][1] = *(const unsigned*)&Kh[r8];
        qfh[t][2] = *(const unsigned*)&Kh[r0 + 8];
        qfh[t][3] = *(const unsigned*)&Kh[r8 + 8];
        qfl[t][0] = *(const unsigned*)&Kl[r0];
        qfl[t][1] = *(const unsigned*)&Kl[r8];
        qfl[t][2] = *(const unsigned*)&Kl[r0 + 8];
        qfl[t][3] = *(const unsigned*)&Kl[r8 + 8];
    }

    float acc[16][4];
#pragma unroll
    for (int nf = 0; nf < 16; nf++)
#pragma unroll
        for (int i = 0; i < 4; i++) acc[nf][i] = 0.f;
    float m0 = -1e30f, m1 = -1e30f, l0 = 0.f, l1 = 0.f;

    const unsigned char* mrowp = mask + (h * NB + qi) * NB;
    const float scl = 0.08838834764831845f;
    unsigned vbase_h = smem_u32(Vh);
    unsigned vbase_l = smem_u32(Vl);
    // per-thread ldmatrix address offset (bytes): row = (j&1)*8 + i, col-block = (j>>1)*8
    int lj = lane >> 3, li = lane & 7;
    unsigned ldsm_off = (unsigned)(((lj & 1) * 8 + li) * KSTR + (lj >> 1) * 8) * 2u;

    for (int kb = 0; kb < NB; kb++) {
        if (!mrowp[kb]) continue;
        __syncthreads();
        for (int idx = tid; idx < 64 * 16; idx += 128) {
            int r = idx >> 4, c = (idx & 15) * 8;
            size_t off = (size_t)(kb * 64 + r) * CCH + h * HD + c;
            *(uint4*)&Kh[r * KSTR + c] = *(const uint4*)(kh + off);
            *(uint4*)&Kl[r * KSTR + c] = *(const uint4*)(kl + off);
            *(uint4*)&Vh[r * KSTR + c] = *(const uint4*)(vh + off);
            *(uint4*)&Vl[r * KSTR + c] = *(const uint4*)(vl + off);
        }
        __syncthreads();

        // ---- S = Q K^T (bf16x3), 16 rows x 64 cols per warp ---------------------
        float sc[8][4];
#pragma unroll
        for (int j = 0; j < 8; j++)
#pragma unroll
            for (int i = 0; i < 4; i++) sc[j][i] = 0.f;

#pragma unroll
        for (int j = 0; j < 8; j++) {
            int rbase = (8 * j + g) * KSTR;
#pragma unroll
            for (int t = 0; t < 8; t++) {
                unsigned bh[2], bl[2];
                bh[0] = *(const unsigned*)&Kh[rbase + 16 * t + tc2];
                bh[1] = *(const unsigned*)&Kh[rbase + 16 * t + 8 + tc2];
                bl[0] = *(const unsigned*)&Kl[rbase + 16 * t + tc2];
                bl[1] = *(const unsigned*)&Kl[rbase + 16 * t + 8 + tc2];
                mma_bf16(sc[j], qfh[t], bh);
                mma_bf16(sc[j], qfh[t], bl);
                mma_bf16(sc[j], qfl[t], bh);
            }
        }

        // ---- online softmax on fragments ---------------------------------------
        float rm0 = -1e30f, rm1 = -1e30f;
#pragma unroll
        for (int j = 0; j < 8; j++) {
#pragma unroll
            for (int i = 0; i < 4; i++) sc[j][i] *= scl;
            rm0 = fmaxf(rm0, fmaxf(sc[j][0], sc[j][1]));
            rm1 = fmaxf(rm1, fmaxf(sc[j][2], sc[j][3]));
        }
        rm0 = fmaxf(rm0, __shfl_xor_sync(0xffffffffu, rm0, 1));
        rm0 = fmaxf(rm0, __shfl_xor_sync(0xffffffffu, rm0, 2));
        rm1 = fmaxf(rm1, __shfl_xor_sync(0xffffffffu, rm1, 1));
        rm1 = fmaxf(rm1, __shfl_xor_sync(0xffffffffu, rm1, 2));
        float mn0 = fmaxf(m0, rm0), mn1 = fmaxf(m1, rm1);
        float es0 = __expf(m0 - mn0), es1 = __expf(m1 - mn1);

        float rs0 = 0.f, rs1 = 0.f;
#pragma unroll
        for (int j = 0; j < 8; j++) {
            sc[j][0] = __expf(sc[j][0] - mn0);
            sc[j][1] = __expf(sc[j][1] - mn0);
            sc[j][2] = __expf(sc[j][2] - mn1);
            sc[j][3] = __expf(sc[j][3] - mn1);
            rs0 += sc[j][0] + sc[j][1];
            rs1 += sc[j][2] + sc[j][3];
        }
        rs0 += __shfl_xor_sync(0xffffffffu, rs0, 1);
        rs0 += __shfl_xor_sync(0xffffffffu, rs0, 2);
        rs1 += __shfl_xor_sync(0xffffffffu, rs1, 1);
        rs1 += __shfl_xor_sync(0xffffffffu, rs1, 2);
        l0 = l0 * es0 + rs0;
        l1 = l1 * es1 + rs1;
        m0 = mn0; m1 = mn1;
#pragma unroll
        for (int nf = 0; nf < 16; nf++) {
            acc[nf][0] *= es0; acc[nf][1] *= es0;
            acc[nf][2] *= es1; acc[nf][3] *= es1;
        }

        // ---- O += P V  (Ph*Vh + Ph*Vl + Pl*Vh) ----------------------------------
#pragma unroll
        for (int t = 0; t < 4; t++) {
            // build P a-frags from C-frags (in registers)
            unsigned ph[4], pl[4];
            {
                float c00 = sc[2 * t][0], c01 = sc[2 * t][1];
                float c02 = sc[2 * t][2], c03 = sc[2 * t][3];
                float c10 = sc[2 * t + 1][0], c11 = sc[2 * t + 1][1];
                float c12 = sc[2 * t + 1][2], c13 = sc[2 * t + 1][3];
                ph[0] = pack_bf16x2(c00, c01);
                ph[1] = pack_bf16x2(c02, c03);
                ph[2] = pack_bf16x2(c10, c11);
                ph[3] = pack_bf16x2(c12, c13);
                float r00 = c00 - __bfloat162float(__float2bfloat16(c00));
                float r01 = c01 - __bfloat162float(__float2bfloat16(c01));
                float r02 = c02 - __bfloat162float(__float2bfloat16(c02));
                float r03 = c03 - __bfloat162float(__float2bfloat16(c03));
                float r10 = c10 - __bfloat162float(__float2bfloat16(c10));
                float r11 = c11 - __bfloat162float(__float2bfloat16(c11));
                float r12 = c12 - __bfloat162float(__float2bfloat16(c12));
                float r13 = c13 - __bfloat162float(__float2bfloat16(c13));
                pl[0] = pack_bf16x2(r00, r01);
                pl[1] = pack_bf16x2(r02, r03);
                pl[2] = pack_bf16x2(r10, r11);
                pl[3] = pack_bf16x2(r12, r13);
            }
            unsigned trow = (unsigned)(16 * t * KSTR) * 2u + ldsm_off;
#pragma unroll
            for (int nfp = 0; nfp < 8; nfp++) {
                unsigned vh0, vh1, vh2, vh3, vl0, vl1, vl2, vl3;
                unsigned coff = trow + (unsigned)(16 * nfp) * 2u;
                ldsm_x4_t(vh0, vh1, vh2, vh3, vbase_h + coff);
                ldsm_x4_t(vl0, vl1, vl2, vl3, vbase_l + coff);
                unsigned bh0[2] = {vh0, vh1}, bh1[2] = {vh2, vh3};
                unsigned bl0[2] = {vl0, vl1}, bl1[2] = {vl2, vl3};
                mma_bf16(acc[2 * nfp], ph, bh0);
                mma_bf16(acc[2 * nfp], ph, bl0);
                mma_bf16(acc[2 * nfp], pl, bh0);
                mma_bf16(acc[2 * nfp + 1], ph, bh1);
                mma_bf16(acc[2 * nfp + 1], ph, bl1);
                mma_bf16(acc[2 * nfp + 1], pl, bh1);
            }
        }
    }

    float inv0 = 1.0f / l0, inv1 = 1.0f / l1;
    int r0 = qi * 64 + wr + g;
    size_t ob = (size_t)r0 * CCH + h * HD;
#pragma unroll
    for (int nf = 0; nf < 16; nf++) {
        int col = 8 * nf + tc2;
        *(float2*)(o + ob + col) = make_float2(acc[nf][0] * inv0, acc[nf][1] * inv0);
        *(float2*)(o + ob + 8 * CCH + col) = make_float2(acc[nf][2] * inv1, acc[nf][3] * inv1);
    }
}

// ---------------- launch ----------------------------------------------------------
extern "C" void kernel_launch(void* const* d_in, const int* in_sizes, int n_in,
                              void* d_out, int out_size)
{
    const float* x        = (const float*)d_in[0];
    const float* rope_cos = (const float*)d_in[1];
    const float* rope_sin = (const float*)d_in[2];
    const void*  sta      = (const void*)d_in[3];
    const float* Wq = (const float*)d_in[4];
    const float* bq = (const float*)d_in[5];
    const float* Wk = (const float*)d_in[6];
    const float* bk = (const float*)d_in[7];
    const float* Wv = (const float*)d_in[8];
    const float* bv = (const float*)d_in[9];
    const float* Wo = (const float*)d_in[10];
    const float* bo = (const float*)d_in[11];
    const float* qn_w = (const float*)d_in[12];
    const float* kn_w = (const float*)d_in[13];
    float* out = (float*)d_out;

    float *qp, *kp, *vp, *ap, *qbp, *kbp;
    unsigned char* mp;
    unsigned short *xh, *xl, *ah, *al;
    unsigned short *qsh, *qsl, *ksh, *ksl, *vsh, *vsl;
    unsigned short *wqh, *wql, *wkh, *wkl, *wvh, *wvl, *woh, *wol;
    cudaGetSymbolAddress((void**)&qp, g_q);
    cudaGetSymbolAddress((void**)&kp, g_k);
    cudaGetSymbolAddress((void**)&vp, g_v);
    cudaGetSymbolAddress((void**)&ap, g_attn);
    cudaGetSymbolAddress((void**)&qbp, g_qb);
    cudaGetSymbolAddress((void**)&kbp, g_kb);
    cudaGetSymbolAddress((void**)&mp, g_mask);
    cudaGetSymbolAddress((void**)&xh, g_xh);
    cudaGetSymbolAddress((void**)&xl, g_xl);
    cudaGetSymbolAddress((void**)&ah, g_ah);
    cudaGetSymbolAddress((void**)&al, g_al);
    cudaGetSymbolAddress((void**)&qsh, g_qsh);
    cudaGetSymbolAddress((void**)&qsl, g_qsl);
    cudaGetSymbolAddress((void**)&ksh, g_ksh);
    cudaGetSymbolAddress((void**)&ksl, g_ksl);
    cudaGetSymbolAddress((void**)&vsh, g_vsh);
    cudaGetSymbolAddress((void**)&vsl, g_vsl);
    cudaGetSymbolAddress((void**)&wqh, g_wqh);
    cudaGetSymbolAddress((void**)&wql, g_wql);
    cudaGetSymbolAddress((void**)&wkh, g_wkh);
    cudaGetSymbolAddress((void**)&wkl, g_wkl);
    cudaGetSymbolAddress((void**)&wvh, g_wvh);
    cudaGetSymbolAddress((void**)&wvl, g_wvl);
    cudaGetSymbolAddress((void**)&woh, g_woh);
    cudaGetSymbolAddress((void**)&wol, g_wol);

    const int NEL = SQ * CCH;
    dim3 tgrid(CCH / 32, CCH / 32), tblk(32, 32);

    split_bf16<<<(NEL + 255) / 256, 256>>>(x, xh, xl, NEL);
    transpose_split<<<tgrid, tblk>>>(Wq, wqh, wql);
    transpose_split<<<tgrid, tblk>>>(Wk, wkh, wkl);
    transpose_split<<<tgrid, tblk>>>(Wv, wvh, wvl);
    transpose_split<<<tgrid, tblk>>>(Wo, woh, wol);

    dim3 ggrid(CCH / BN, SQ / BM);
    gemm_tc<<<ggrid, 256>>>(xh, xl, wqh, wql, bq, qp);
    gemm_tc<<<ggrid, 256>>>(xh, xl, wkh, wkl, bk, kp);
    gemm_tc<<<ggrid, 256>>>(xh, xl, wvh, wvl, bv, vp);

    int nwarp_blocks = (SQ * NH) / 8;
    rmsnorm_rope_split<<<nwarp_blocks, 256>>>(qp, qn_w, rope_cos, rope_sin, qsh, qsl);
    rmsnorm_rope_split<<<nwarp_blocks, 256>>>(kp, kn_w, rope_cos, rope_sin, ksh, ksl);
    split_bf16<<<(NEL + 255) / 256, 256>>>(vp, vsh, vsl, NEL);

    pool_blocks<<<dim3(NH, NB), 128>>>(qp, qbp);
    pool_blocks<<<dim3(NH, NB), 128>>>(kp, kbp);

    nabla_mask<<<dim3(NH, NB), 32>>>(qbp, kbp, sta, mp);

    cudaFuncSetAttribute(flash_attn_tc, cudaFuncAttributeMaxDynamicSharedMemorySize, FT_SMEM);
    flash_attn_tc<<<dim3(NB, NH), 128, FT_SMEM>>>(qsh, qsl, ksh, ksl, vsh, vsl, mp, ap);

    split_bf16<<<(NEL + 255) / 256, 256>>>(ap, ah, al, NEL);
    gemm_tc<<<ggrid, 256>>>(ah, al, woh, wol, bo, out);
}

// round 7
// speedup vs baseline: 3.6607x; 1.3768x over previous
#include <cuda_runtime.h>
#include <cuda_bf16.h>
#include <math.h>

#define SQ   2048
#define CCH  2048
#define NH   16
#define HD   128
#define BLKS 64
#define NB   32
#define THRP 0.8f
#define EPSV 1e-6f

// ---------------- scratch (device globals; no allocation allowed) -------------
__device__ float g_q[SQ * CCH];
__device__ float g_k[SQ * CCH];
__device__ float g_v[SQ * CCH];
__device__ float g_qb[NH * NB * HD];
__device__ float g_kb[NH * NB * HD];
__device__ unsigned char g_mask[NH * NB * NB];

// bf16 split buffers (stored as ushort)
__device__ unsigned short g_xh[SQ * CCH];
__device__ unsigned short g_xl[SQ * CCH];
__device__ unsigned short g_ah[SQ * CCH];   // attention output hi (written by flash)
__device__ unsigned short g_al[SQ * CCH];   // attention output lo
__device__ unsigned short g_qsh[SQ * CCH];
__device__ unsigned short g_qsl[SQ * CCH];
__device__ unsigned short g_ksh[SQ * CCH];
__device__ unsigned short g_ksl[SQ * CCH];
__device__ unsigned short g_vsh[SQ * CCH];
__device__ unsigned short g_vsl[SQ * CCH];
__device__ unsigned short g_wqh[CCH * CCH];
__device__ unsigned short g_wql[CCH * CCH];
__device__ unsigned short g_wkh[CCH * CCH];
__device__ unsigned short g_wkl[CCH * CCH];
__device__ unsigned short g_wvh[CCH * CCH];
__device__ unsigned short g_wvl[CCH * CCH];
__device__ unsigned short g_woh[CCH * CCH];
__device__ unsigned short g_wol[CCH * CCH];

// ================= helpers ======================================================
__device__ __forceinline__ unsigned pack_bf16x2(float lo, float hi) {
    unsigned r;
    asm("cvt.rn.bf16x2.f32 %0, %1, %2;" : "=r"(r) : "f"(hi), "f"(lo));
    return r;
}
__device__ __forceinline__ unsigned smem_u32(const void* p) {
    unsigned a;
    asm("{ .reg .u64 t; cvta.to.shared.u64 t, %1; cvt.u32.u64 %0, t; }" : "=r"(a) : "l"(p));
    return a;
}
__device__ __forceinline__ void mma_bf16(float* c, const unsigned* a, const unsigned* b)
{
    asm volatile(
        "mma.sync.aligned.m16n8k16.row.col.f32.bf16.bf16.f32 "
        "{%0,%1,%2,%3}, {%4,%5,%6,%7}, {%8,%9}, {%0,%1,%2,%3};"
        : "+f"(c[0]), "+f"(c[1]), "+f"(c[2]), "+f"(c[3])
        : "r"(a[0]), "r"(a[1]), "r"(a[2]), "r"(a[3]), "r"(b[0]), "r"(b[1]));
}
__device__ __forceinline__ void ldsm_x4_t(unsigned& r0, unsigned& r1, unsigned& r2, unsigned& r3,
                                          unsigned addr)
{
    asm volatile("ldmatrix.sync.aligned.m8n8.x4.trans.shared.b16 {%0,%1,%2,%3}, [%4];"
                 : "=r"(r0), "=r"(r1), "=r"(r2), "=r"(r3) : "r"(addr));
}
__device__ __forceinline__ void cp16(unsigned sm, const void* g) {
    asm volatile("cp.async.cg.shared.global [%0], [%1], 16;" :: "r"(sm), "l"(g));
}
#define CP_COMMIT() asm volatile("cp.async.commit_group;" ::: "memory")

// ================= fp32 -> bf16 hi/lo split ====================================
__global__ void split_bf16(const float* __restrict__ a, unsigned short* __restrict__ h,
                           unsigned short* __restrict__ l, int n)
{
    int i = blockIdx.x * 256 + threadIdx.x;
    if (i < n) {
        float v = a[i];
        __nv_bfloat16 hi = __float2bfloat16(v);
        __nv_bfloat16 lo = __float2bfloat16(v - __bfloat162float(hi));
        h[i] = __bfloat16_as_ushort(hi);
        l[i] = __bfloat16_as_ushort(lo);
    }
}

// ================= transpose + split: W[K][N] -> T[N][K] hi/lo bf16 ============
__global__ void transpose_split(const float* __restrict__ W,
                                unsigned short* __restrict__ Th, unsigned short* __restrict__ Tl)
{
    __shared__ float t[32][33];
    int bx = blockIdx.x * 32, by = blockIdx.y * 32;
    int tx = threadIdx.x, ty = threadIdx.y;
    t[ty][tx] = W[(size_t)(by + ty) * CCH + bx + tx];
    __syncthreads();
    float v = t[tx][ty];
    __nv_bfloat16 hi = __float2bfloat16(v);
    __nv_bfloat16 lo = __float2bfloat16(v - __bfloat162float(hi));
    size_t o = (size_t)(bx + ty) * CCH + by + tx;
    Th[o] = __bfloat16_as_ushort(hi);
    Tl[o] = __bfloat16_as_ushort(lo);
}

// ================= HMMA bf16x3 GEMM, 128x128 tile, cp.async 2-stage =============
#define BM 128
#define BN 128
#define BK 32
#define ASTR 40
#define TILE_U16 (128 * ASTR)
#define STAGE_U16 (4 * TILE_U16)
#define G2SMEM (2 * STAGE_U16 * 2)

__global__ __launch_bounds__(256) void gemm_tc(
    const unsigned short* __restrict__ Ah, const unsigned short* __restrict__ Al,
    const unsigned short* __restrict__ Bh, const unsigned short* __restrict__ Bl,
    const float* __restrict__ bias, float* __restrict__ Co)
{
    extern __shared__ __align__(16) unsigned short smg[];
    unsigned sbase = smem_u32(smg);

    int tid = threadIdx.x, w = tid >> 5, lane = tid & 31;
    int g = lane >> 2, tc2 = (lane & 3) * 2;
    int m0 = blockIdx.y * BM, n0 = blockIdx.x * BN;
    int wm = (w >> 2) * 64, wn = (w & 3) * 32;

    float acc[4][4][4];
#pragma unroll
    for (int i = 0; i < 4; i++)
#pragma unroll
        for (int j = 0; j < 4; j++)
#pragma unroll
            for (int l = 0; l < 4; l++) acc[i][j][l] = 0.f;

    // per-thread load slots: two uint4 per tile (512 uint4 / tile / 256 threads)
    int r0l = tid >> 2, c0l = (tid & 3) * 8;
    int r1l = (tid + 256) >> 2, c1l = ((tid + 256) & 3) * 8;

    const int NCK = CCH / BK;

#define LOAD_STAGE(CK, SOFF)                                                        \
    {                                                                               \
        int kb = (CK) * BK;                                                         \
        unsigned s0 = sbase + (SOFF) + (unsigned)(r0l * ASTR + c0l) * 2u;           \
        unsigned s1 = sbase + (SOFF) + (unsigned)(r1l * ASTR + c1l) * 2u;           \
        size_t ga0 = (size_t)(m0 + r0l) * CCH + kb + c0l;                           \
        size_t ga1 = (size_t)(m0 + r1l) * CCH + kb + c1l;                           \
        size_t gb0 = (size_t)(n0 + r0l) * CCH + kb + c0l;                           \
        size_t gb1 = (size_t)(n0 + r1l) * CCH + kb + c1l;                           \
        cp16(s0, Ah + ga0);                                                         \
        cp16(s1, Ah + ga1);                                                         \
        cp16(s0 + TILE_U16 * 2u, Al + ga0);                                         \
        cp16(s1 + TILE_U16 * 2u, Al + ga1);                                         \
        cp16(s0 + 2u * TILE_U16 * 2u, Bh + gb0);                                    \
        cp16(s1 + 2u * TILE_U16 * 2u, Bh + gb1);                                    \
        cp16(s0 + 3u * TILE_U16 * 2u, Bl + gb0);                                    \
        cp16(s1 + 3u * TILE_U16 * 2u, Bl + gb1);                                    \
    }

    LOAD_STAGE(0, 0u);
    CP_COMMIT();

    for (int ck = 0; ck < NCK; ck++) {
        if (ck + 1 < NCK) {
            LOAD_STAGE(ck + 1, (unsigned)(((ck + 1) & 1) * STAGE_U16 * 2));
            CP_COMMIT();
            asm volatile("cp.async.wait_group 1;" ::: "memory");
        } else {
            asm volatile("cp.async.wait_group 0;" ::: "memory");
        }
        __syncthreads();

        const unsigned short* st = smg + (ck & 1) * STAGE_U16;
        const unsigned short* sAh = st;
        const unsigned short* sAl = st + TILE_U16;
        const unsigned short* sBh = st + 2 * TILE_U16;
        const unsigned short* sBl = st + 3 * TILE_U16;

#pragma unroll
        for (int ks = 0; ks < BK; ks += 16) {
            unsigned ah[4][4], al[4][4], bh[4][2], bl[4][2];
#pragma unroll
            for (int mf = 0; mf < 4; mf++) {
                int r = (wm + mf * 16 + g) * ASTR;
                ah[mf][0] = *(const unsigned*)&sAh[r + ks + tc2];
                ah[mf][1] = *(const unsigned*)&sAh[r + 8 * ASTR + ks + tc2];
                ah[mf][2] = *(const unsigned*)&sAh[r + ks + 8 + tc2];
                ah[mf][3] = *(const unsigned*)&sAh[r + 8 * ASTR + ks + 8 + tc2];
                al[mf][0] = *(const unsigned*)&sAl[r + ks + tc2];
                al[mf][1] = *(const unsigned*)&sAl[r + 8 * ASTR + ks + tc2];
                al[mf][2] = *(const unsigned*)&sAl[r + ks + 8 + tc2];
                al[mf][3] = *(const unsigned*)&sAl[r + 8 * ASTR + ks + 8 + tc2];
            }
#pragma unroll
            for (int nf = 0; nf < 4; nf++) {
                int r = (wn + nf * 8 + g) * ASTR;
                bh[nf][0] = *(const unsigned*)&sBh[r + ks + tc2];
                bh[nf][1] = *(const unsigned*)&sBh[r + ks + 8 + tc2];
                bl[nf][0] = *(const unsigned*)&sBl[r + ks + tc2];
                bl[nf][1] = *(const unsigned*)&sBl[r + ks + 8 + tc2];
            }
#pragma unroll
            for (int mf = 0; mf < 4; mf++)
#pragma unroll
                for (int nf = 0; nf < 4; nf++) {
                    mma_bf16(acc[mf][nf], ah[mf], bh[nf]);
                    mma_bf16(acc[mf][nf], ah[mf], bl[nf]);
                    mma_bf16(acc[mf][nf], al[mf], bh[nf]);
                }
        }
        __syncthreads();
    }

#pragma unroll
    for (int mf = 0; mf < 4; mf++) {
        int r0 = m0 + wm + mf * 16 + g;
#pragma unroll
        for (int nf = 0; nf < 4; nf++) {
            int col = n0 + wn + nf * 8 + tc2;
            float bx = bias[col], by = bias[col + 1];
            float2 lo = make_float2(acc[mf][nf][0] + bx, acc[mf][nf][1] + by);
            float2 hi = make_float2(acc[mf][nf][2] + bx, acc[mf][nf][3] + by);
            *(float2*)(Co + (size_t)r0 * CCH + col) = lo;
            *(float2*)(Co + (size_t)(r0 + 8) * CCH + col) = hi;
        }
    }
}

// ---------------- fused RMSNorm + RoPE + bf16 split, in-place ------------------
__global__ __launch_bounds__(256) void rmsnorm_rope_split(
    float* __restrict__ buf, const float* __restrict__ w,
    const float* __restrict__ cs, const float* __restrict__ sn,
    unsigned short* __restrict__ oh, unsigned short* __restrict__ ol)
{
    int warp = (blockIdx.x * blockDim.x + threadIdx.x) >> 5;
    int lane = threadIdx.x & 31;
    if (warp >= SQ * NH) return;
    int s = warp / NH, h = warp % NH;
    size_t base = (size_t)s * CCH + h * HD;
    float* row = buf + base;

    float x0 = row[lane], x1 = row[lane + 32], x2 = row[lane + 64], x3 = row[lane + 96];
    float ss = x0 * x0 + x1 * x1 + x2 * x2 + x3 * x3;
#pragma unroll
    for (int o = 16; o; o >>= 1) ss += __shfl_xor_sync(0xffffffffu, ss, o);
    float r = rsqrtf(ss * (1.0f / HD) + EPSV);

    float y0 = x0 * r * w[lane];
    float y1 = x1 * r * w[lane + 32];
    float y2 = x2 * r * w[lane + 64];
    float y3 = x3 * r * w[lane + 96];

    const float* cr = cs + (size_t)s * HD;
    const float* sr = sn + (size_t)s * HD;
    float z0 = y0 * cr[lane]      - y2 * sr[lane];
    float z1 = y1 * cr[lane + 32] - y3 * sr[lane + 32];
    float z2 = y2 * cr[lane + 64] + y0 * sr[lane + 64];
    float z3 = y3 * cr[lane + 96] + y1 * sr[lane + 96];

    row[lane] = z0; row[lane + 32] = z1; row[lane + 64] = z2; row[lane + 96] = z3;

    float zz[4] = {z0, z1, z2, z3};
#pragma unroll
    for (int i = 0; i < 4; i++) {
        __nv_bfloat16 hi = __float2bfloat16(zz[i]);
        __nv_bfloat16 lo = __float2bfloat16(zz[i] - __bfloat162float(hi));
        oh[base + lane + 32 * i] = __bfloat16_as_ushort(hi);
        ol[base + lane + 32 * i] = __bfloat16_as_ushort(lo);
    }
}

// ---------------- block pooling ------------------------------------------------
__global__ void pool_blocks(const float* __restrict__ buf, float* __restrict__ out)
{
    int h = blockIdx.x, b = blockIdx.y, d = threadIdx.x;
    float sum = 0.f;
#pragma unroll 8
    for (int i = 0; i < BLKS; i++)
        sum += buf[(size_t)(b * BLKS + i) * CCH + h * HD + d];
    out[((h * NB) + b) * HD + d] = sum * (1.0f / BLKS);
}

// ---------------- NABLA block mask ----------------------------------------------
__device__ __forceinline__ int sniff_sta_dtype(const unsigned int* w)
{
    bool all01 = true, allf = true;
    for (int i = 0; i < 256; i++) {
        unsigned int v = w[i];
        if (v > 1u) all01 = false;
        if (v != 0u && v != 0x3F800000u) allf = false;
    }
    if (all01) return 0;
    if (allf) return 1;
    return 2;
}

__global__ void nabla_mask(const float* __restrict__ qb, const float* __restrict__ kb,
                           const void* __restrict__ sta, unsigned char* __restrict__ mask)
{
    int h = blockIdx.x, q = blockIdx.y, k = threadIdx.x;
    __shared__ float p[NB];
    __shared__ float cutoff;
    __shared__ int sdt;
    if (k == 0) sdt = sniff_sta_dtype((const unsigned int*)sta);

    const float* qr = qb + (h * NB + q) * HD;
    const float* kr = kb + (h * NB + k) * HD;
    float dot = 0.f;
#pragma unroll 16
    for (int d = 0; d < HD; d++) dot += qr[d] * kr[d];
    p[k] = dot * 0.08838834764831845f;
    __syncthreads();
    if (k == 0) {
        float mx = -1e30f;
        for (int i = 0; i < NB; i++) mx = fmaxf(mx, p[i]);
        float sum = 0.f;
        for (int i = 0; i < NB; i++) { p[i] = expf(p[i] - mx); sum += p[i]; }
        float inv = 1.0f / sum;
        float srt[NB];
        for (int i = 0; i < NB; i++) { p[i] *= inv; srt[i] = p[i]; }
        for (int i = 1; i < NB; i++) {
            float v = srt[i];
            int j = i - 1;
            while (j >= 0 && srt[j] < v) { srt[j + 1] = srt[j]; j--; }
            srt[j + 1] = v;
        }
        float run = 0.f, co = 1e30f;
        for (int i = 0; i < NB; i++) {
            if (run < THRP) { co = srt[i]; run += srt[i]; }
        }
        cutoff = co;
    }
    __syncthreads();

    bool sta_on;
    int sidx = q * NB + k;
    if (sdt == 0)      sta_on = ((const int*)sta)[sidx] != 0;
    else if (sdt == 1) sta_on = ((const float*)sta)[sidx] != 0.0f;
    else               sta_on = ((const unsigned char*)sta)[sidx] != 0;

    unsigned char keep = (p[k] >= cutoff) || sta_on;
    mask[(h * NB + q) * NB + k] = keep;
}

// ---------------- HMMA block-sparse flash attention ------------------------------
#define KSTR 136
#define FT_SMEM (4 * 64 * KSTR * 2)

__global__ __launch_bounds__(128) void flash_attn_tc(
    const unsigned short* __restrict__ qh, const unsigned short* __restrict__ ql,
    const unsigned short* __restrict__ kh, const unsigned short* __restrict__ kl,
    const unsigned short* __restrict__ vh, const unsigned short* __restrict__ vl,
    const unsigned char* __restrict__ mask,
    unsigned short* __restrict__ oh, unsigned short* __restrict__ ol)
{
    extern __shared__ __align__(16) unsigned short smu[];
    unsigned short* Kh = smu;
    unsigned short* Kl = Kh + 64 * KSTR;
    unsigned short* Vh = Kl + 64 * KSTR;
    unsigned short* Vl = Vh + 64 * KSTR;

    int qi = blockIdx.x, h = blockIdx.y;
    int tid = threadIdx.x, w = tid >> 5, lane = tid & 31;
    int g = lane >> 2, tc2 = (lane & 3) * 2;
    int wr = w * 16;

    for (int idx = tid; idx < 64 * 16; idx += 128) {
        int r = idx >> 4, c = (idx & 15) * 8;
        size_t off = (size_t)(qi * 64 + r) * CCH + h * HD + c;
        *(uint4*)&Kh[r * KSTR + c] = *(const uint4*)(qh + off);
        *(uint4*)&Kl[r * KSTR + c] = *(const uint4*)(ql + off);
    }
    __syncthreads();

    unsigned qfh[8][4], qfl[8][4];
#pragma unroll
    for (int t = 0; t < 8; t++) {
        int r0 = (wr + g) * KSTR + 16 * t + tc2;
        int r8 = (wr + 8 + g) * KSTR + 16 * t + tc2;
        qfh[t][0] = *(const unsigned*)&Kh[r0];
        qfh[t][1] = *(const unsigned*)&Kh[r8];
        qfh[t][2] = *(const unsigned*)&Kh[r0 + 8];
        qfh[t][3] = *(const unsigned*)&Kh[r8 + 8];
        qfl[t][0] = *(const unsigned*)&Kl[r0];
        qfl[t][1] = *(const unsigned*)&Kl[r8];
        qfl[t][2] = *(const unsigned*)&Kl[r0 + 8];
        qfl[t][3] = *(const unsigned*)&Kl[r8 + 8];
    }

    float acc[16][4];
#pragma unroll
    for (int nf = 0; nf < 16; nf++)
#pragma unroll
        for (int i = 0; i < 4; i++) acc[nf][i] = 0.f;
    float m0 = -1e30f, m1 = -1e30f, l0 = 0.f, l1 = 0.f;

    const unsigned char* mrowp = mask + (h * NB + qi) * NB;
    const float scl = 0.08838834764831845f;
    unsigned vbase_h = smem_u32(Vh);
    unsigned vbase_l = smem_u32(Vl);
    int lj = lane >> 3, li = lane & 7;
    unsigned ldsm_off = (unsigned)(((lj & 1) * 8 + li) * KSTR + (lj >> 1) * 8) * 2u;

    for (int kb = 0; kb < NB; kb++) {
        if (!mrowp[kb]) continue;
        __syncthreads();
        for (int idx = tid; idx < 64 * 16; idx += 128) {
            int r = idx >> 4, c = (idx & 15) * 8;
            size_t off = (size_t)(kb * 64 + r) * CCH + h * HD + c;
            *(uint4*)&Kh[r * KSTR + c] = *(const uint4*)(kh + off);
            *(uint4*)&Kl[r * KSTR + c] = *(const uint4*)(kl + off);
            *(uint4*)&Vh[r * KSTR + c] = *(const uint4*)(vh + off);
            *(uint4*)&Vl[r * KSTR + c] = *(const uint4*)(vl + off);
        }
        __syncthreads();

        float sc[8][4];
#pragma unroll
        for (int j = 0; j < 8; j++)
#pragma unroll
            for (int i = 0; i < 4; i++) sc[j][i] = 0.f;

#pragma unroll
        for (int j = 0; j < 8; j++) {
            int rbase = (8 * j + g) * KSTR;
#pragma unroll
            for (int t = 0; t < 8; t++) {
                unsigned bh[2], bl[2];
                bh[0] = *(const unsigned*)&Kh[rbase + 16 * t + tc2];
                bh[1] = *(const unsigned*)&Kh[rbase + 16 * t + 8 + tc2];
                bl[0] = *(const unsigned*)&Kl[rbase + 16 * t + tc2];
                bl[1] = *(const unsigned*)&Kl[rbase + 16 * t + 8 + tc2];
                mma_bf16(sc[j], qfh[t], bh);
                mma_bf16(sc[j], qfh[t], bl);
                mma_bf16(sc[j], qfl[t], bh);
            }
        }

        float rm0 = -1e30f, rm1 = -1e30f;
#pragma unroll
        for (int j = 0; j < 8; j++) {
#pragma unroll
            for (int i = 0; i < 4; i++) sc[j][i] *= scl;
            rm0 = fmaxf(rm0, fmaxf(sc[j][0], sc[j][1]));
            rm1 = fmaxf(rm1, fmaxf(sc[j][2], sc[j][3]));
        }
        rm0 = fmaxf(rm0, __shfl_xor_sync(0xffffffffu, rm0, 1));
        rm0 = fmaxf(rm0, __shfl_xor_sync(0xffffffffu, rm0, 2));
        rm1 = fmaxf(rm1, __shfl_xor_sync(0xffffffffu, rm1, 1));
        rm1 = fmaxf(rm1, __shfl_xor_sync(0xffffffffu, rm1, 2));
        float mn0 = fmaxf(m0, rm0), mn1 = fmaxf(m1, rm1);
        float es0 = __expf(m0 - mn0), es1 = __expf(m1 - mn1);

        float rs0 = 0.f, rs1 = 0.f;
#pragma unroll
        for (int j = 0; j < 8; j++) {
            sc[j][0] = __expf(sc[j][0] - mn0);
            sc[j][1] = __expf(sc[j][1] - mn0);
            sc[j][2] = __expf(sc[j][2] - mn1);
            sc[j][3] = __expf(sc[j][3] - mn1);
            rs0 += sc[j][0] + sc[j][1];
            rs1 += sc[j][2] + sc[j][3];
        }
        rs0 += __shfl_xor_sync(0xffffffffu, rs0, 1);
        rs0 += __shfl_xor_sync(0xffffffffu, rs0, 2);
        rs1 += __shfl_xor_sync(0xffffffffu, rs1, 1);
        rs1 += __shfl_xor_sync(0xffffffffu, rs1, 2);
        l0 = l0 * es0 + rs0;
        l1 = l1 * es1 + rs1;
        m0 = mn0; m1 = mn1;
#pragma unroll
        for (int nf = 0; nf < 16; nf++) {
            acc[nf][0] *= es0; acc[nf][1] *= es0;
            acc[nf][2] *= es1; acc[nf][3] *= es1;
        }

#pragma unroll
        for (int t = 0; t < 4; t++) {
            unsigned ph[4], pl[4];
            {
                float c00 = sc[2 * t][0], c01 = sc[2 * t][1];
                float c02 = sc[2 * t][2], c03 = sc[2 * t][3];
                float c10 = sc[2 * t + 1][0], c11 = sc[2 * t + 1][1];
                float c12 = sc[2 * t + 1][2], c13 = sc[2 * t + 1][3];
                ph[0] = pack_bf16x2(c00, c01);
                ph[1] = pack_bf16x2(c02, c03);
                ph[2] = pack_bf16x2(c10, c11);
                ph[3] = pack_bf16x2(c12, c13);
                float r00 = c00 - __bfloat162float(__float2bfloat16(c00));
                float r01 = c01 - __bfloat162float(__float2bfloat16(c01));
                float r02 = c02 - __bfloat162float(__float2bfloat16(c02));
                float r03 = c03 - __bfloat162float(__float2bfloat16(c03));
                float r10 = c10 - __bfloat162float(__float2bfloat16(c10));
                float r11 = c11 - __bfloat162float(__float2bfloat16(c11));
                float r12 = c12 - __bfloat162float(__float2bfloat16(c12));
                float r13 = c13 - __bfloat162float(__float2bfloat16(c13));
                pl[0] = pack_bf16x2(r00, r01);
                pl[1] = pack_bf16x2(r02, r03);
                pl[2] = pack_bf16x2(r10, r11);
                pl[3] = pack_bf16x2(r12, r13);
            }
            unsigned trow = (unsigned)(16 * t * KSTR) * 2u + ldsm_off;
#pragma unroll
            for (int nfp = 0; nfp < 8; nfp++) {
                unsigned vh0, vh1, vh2, vh3, vl0, vl1, vl2, vl3;
                unsigned coff = trow + (unsigned)(16 * nfp) * 2u;
                ldsm_x4_t(vh0, vh1, vh2, vh3, vbase_h + coff);
                ldsm_x4_t(vl0, vl1, vl2, vl3, vbase_l + coff);
                unsigned bh0[2] = {vh0, vh1}, bh1[2] = {vh2, vh3};
                unsigned bl0[2] = {vl0, vl1}, bl1[2] = {vl2, vl3};
                mma_bf16(acc[2 * nfp], ph, bh0);
                mma_bf16(acc[2 * nfp], ph, bl0);
                mma_bf16(acc[2 * nfp], pl, bh0);
                mma_bf16(acc[2 * nfp + 1], ph, bh1);
                mma_bf16(acc[2 * nfp + 1], ph, bl1);
                mma_bf16(acc[2 * nfp + 1], pl, bh1);
            }
        }
    }

    // epilogue: normalize + bf16 hi/lo split, write directly to GEMM input bufs
    float inv0 = 1.0f / l0, inv1 = 1.0f / l1;
    int r0 = qi * 64 + wr + g;
    size_t ob = (size_t)r0 * CCH + h * HD;
#pragma unroll
    for (int nf = 0; nf < 16; nf++) {
        int col = 8 * nf + tc2;
        float v0 = acc[nf][0] * inv0, v1 = acc[nf][1] * inv0;
        float v2 = acc[nf][2] * inv1, v3 = acc[nf][3] * inv1;
        __nv_bfloat16 b0 = __float2bfloat16(v0), b1 = __float2bfloat16(v1);
        __nv_bfloat16 b2 = __float2bfloat16(v2), b3 = __float2bfloat16(v3);
        float q0 = v0 - __bfloat162float(b0), q1 = v1 - __bfloat162float(b1);
        float q2 = v2 - __bfloat162float(b2), q3 = v3 - __bfloat162float(b3);
        *(unsigned*)&oh[ob + col] =
            ((unsigned)__bfloat16_as_ushort(b1) << 16) | __bfloat16_as_ushort(b0);
        *(unsigned*)&oh[ob + 8 * CCH + col] =
            ((unsigned)__bfloat16_as_ushort(b3) << 16) | __bfloat16_as_ushort(b2);
        *(unsigned*)&ol[ob + col] = pack_bf16x2(q0, q1);
        *(unsigned*)&ol[ob + 8 * CCH + col] = pack_bf16x2(q2, q3);
    }
}

// ---------------- launch ----------------------------------------------------------
extern "C" void kernel_launch(void* const* d_in, const int* in_sizes, int n_in,
                              void* d_out, int out_size)
{
    const float* x        = (const float*)d_in[0];
    const float* rope_cos = (const float*)d_in[1];
    const float* rope_sin = (const float*)d_in[2];
    const void*  sta      = (const void*)d_in[3];
    const float* Wq = (const float*)d_in[4];
    const float* bq = (const float*)d_in[5];
    const float* Wk = (const float*)d_in[6];
    const float* bk = (const float*)d_in[7];
    const float* Wv = (const float*)d_in[8];
    const float* bv = (const float*)d_in[9];
    const float* Wo = (const float*)d_in[10];
    const float* bo = (const float*)d_in[11];
    const float* qn_w = (const float*)d_in[12];
    const float* kn_w = (const float*)d_in[13];
    float* out = (float*)d_out;

    float *qp, *kp, *vp, *qbp, *kbp;
    unsigned char* mp;
    unsigned short *xh, *xl, *ah, *al;
    unsigned short *qsh, *qsl, *ksh, *ksl, *vsh, *vsl;
    unsigned short *wqh, *wql, *wkh, *wkl, *wvh, *wvl, *woh, *wol;
    cudaGetSymbolAddress((void**)&qp, g_q);
    cudaGetSymbolAddress((void**)&kp, g_k);
    cudaGetSymbolAddress((void**)&vp, g_v);
    cudaGetSymbolAddress((void**)&qbp, g_qb);
    cudaGetSymbolAddress((void**)&kbp, g_kb);
    cudaGetSymbolAddress((void**)&mp, g_mask);
    cudaGetSymbolAddress((void**)&xh, g_xh);
    cudaGetSymbolAddress((void**)&xl, g_xl);
    cudaGetSymbolAddress((void**)&ah, g_ah);
    cudaGetSymbolAddress((void**)&al, g_al);
    cudaGetSymbolAddress((void**)&qsh, g_qsh);
    cudaGetSymbolAddress((void**)&qsl, g_qsl);
    cudaGetSymbolAddress((void**)&ksh, g_ksh);
    cudaGetSymbolAddress((void**)&ksl, g_ksl);
    cudaGetSymbolAddress((void**)&vsh, g_vsh);
    cudaGetSymbolAddress((void**)&vsl, g_vsl);
    cudaGetSymbolAddress((void**)&wqh, g_wqh);
    cudaGetSymbolAddress((void**)&wql, g_wql);
    cudaGetSymbolAddress((void**)&wkh, g_wkh);
    cudaGetSymbolAddress((void**)&wkl, g_wkl);
    cudaGetSymbolAddress((void**)&wvh, g_wvh);
    cudaGetSymbolAddress((void**)&wvl, g_wvl);
    cudaGetSymbolAddress((void**)&woh, g_woh);
    cudaGetSymbolAddress((void**)&wol, g_wol);

    const int NEL = SQ * CCH;
    dim3 tgrid(CCH / 32, CCH / 32), tblk(32, 32);

    split_bf16<<<(NEL + 255) / 256, 256>>>(x, xh, xl, NEL);
    transpose_split<<<tgrid, tblk>>>(Wq, wqh, wql);
    transpose_split<<<tgrid, tblk>>>(Wk, wkh, wkl);
    transpose_split<<<tgrid, tblk>>>(Wv, wvh, wvl);
    transpose_split<<<tgrid, tblk>>>(Wo, woh, wol);

    cudaFuncSetAttribute(gemm_tc, cudaFuncAttributeMaxDynamicSharedMemorySize, G2SMEM);
    dim3 ggrid(CCH / BN, SQ / BM);
    gemm_tc<<<ggrid, 256, G2SMEM>>>(xh, xl, wqh, wql, bq, qp);
    gemm_tc<<<ggrid, 256, G2SMEM>>>(xh, xl, wkh, wkl, bk, kp);
    gemm_tc<<<ggrid, 256, G2SMEM>>>(xh, xl, wvh, wvl, bv, vp);

    int nwarp_blocks = (SQ * NH) / 8;
    rmsnorm_rope_split<<<nwarp_blocks, 256>>>(qp, qn_w, rope_cos, rope_sin, qsh, qsl);
    rmsnorm_rope_split<<<nwarp_blocks, 256>>>(kp, kn_w, rope_cos, rope_sin, ksh, ksl);
    split_bf16<<<(NEL + 255) / 256, 256>>>(vp, vsh, vsl, NEL);

    pool_blocks<<<dim3(NH, NB), 128>>>(qp, qbp);
    pool_blocks<<<dim3(NH, NB), 128>>>(kp, kbp);

    nabla_mask<<<dim3(NH, NB), 32>>>(qbp, kbp, sta, mp);

    cudaFuncSetAttribute(flash_attn_tc, cudaFuncAttributeMaxDynamicSharedMemorySize, FT_SMEM);
    flash_attn_tc<<<dim3(NB, NH), 128, FT_SMEM>>>(qsh, qsl, ksh, ksl, vsh, vsl, mp, ah, al);

    gemm_tc<<<ggrid, 256, G2SMEM>>>(ah, al, woh, wol, bo, out);
}